// round 2
// baseline (speedup 1.0000x reference)
#include <cuda_runtime.h>
#include <math.h>

#define BB   8
#define SEQ  1024
#define DD   768
#define HH   12
#define DHH  64
#define HD   768            // HH*DHH
#define TOK  (BB*SEQ)       // 8192

// -------- scratch (static device globals; no allocs allowed) --------
__device__ float g_q[(size_t)TOK*HD];
__device__ float g_k[(size_t)TOK*HD];
__device__ float g_v[(size_t)TOK*HD];
__device__ float g_o[(size_t)TOK*HD];
__device__ float g_s[(size_t)BB*HH*SEQ*SEQ];   // 402 MB attention scores

// -------- tiled fp32 GEMM: C[m,n] = sum_k A[m,k] * B[n,k]  (NT) --------
// BM=128, BN=64, BK=16, 256 threads, 8x4 per-thread microtile.
// Batched via blockIdx.z with two-level (outer/inner) stride decomposition:
//   off = (z / nzi) * s?o + (z % nzi) * s?i
#define GBM 128
#define GBN 64
#define GBK 16
#define GTM 8
#define GTN 4

__global__ __launch_bounds__(256) void gemm_nt(
    const float* __restrict__ A, const float* __restrict__ Bw, float* __restrict__ C,
    int M, int Nn, int K, int lda, int ldb, int ldc,
    int nzi, long long sAo, long long sAi, long long sBo, long long sBi,
    long long sCo, long long sCi)
{
    int z = blockIdx.z;
    A  += (long long)(z / nzi) * sAo + (long long)(z % nzi) * sAi;
    Bw += (long long)(z / nzi) * sBo + (long long)(z % nzi) * sBi;
    C  += (long long)(z / nzi) * sCo + (long long)(z % nzi) * sCi;

    __shared__ float As[GBK][GBM];
    __shared__ float Bs[GBK][GBN];

    int t  = threadIdx.x;
    int m0 = blockIdx.y * GBM;
    int n0 = blockIdx.x * GBN;
    int ty = t >> 4;        // 0..15
    int tx = t & 15;        // 0..15

    float acc[GTM][GTN];
#pragma unroll
    for (int i = 0; i < GTM; i++)
#pragma unroll
        for (int j = 0; j < GTN; j++) acc[i][j] = 0.f;

    int ar = t >> 2;        // 0..63
    int ac = (t & 3) * 4;   // 0,4,8,12

    for (int kt = 0; kt < K; kt += GBK) {
#pragma unroll
        for (int r = 0; r < 2; r++) {
            int row = ar + r * 64;
            float4 av = *(const float4*)(A + (size_t)(m0 + row) * lda + kt + ac);
            As[ac + 0][row] = av.x; As[ac + 1][row] = av.y;
            As[ac + 2][row] = av.z; As[ac + 3][row] = av.w;
        }
        {
            float4 bv = *(const float4*)(Bw + (size_t)(n0 + ar) * ldb + kt + ac);
            Bs[ac + 0][ar] = bv.x; Bs[ac + 1][ar] = bv.y;
            Bs[ac + 2][ar] = bv.z; Bs[ac + 3][ar] = bv.w;
        }
        __syncthreads();
#pragma unroll
        for (int kk = 0; kk < GBK; kk++) {
            float4 a0 = *(const float4*)&As[kk][ty * GTM];
            float4 a1 = *(const float4*)&As[kk][ty * GTM + 4];
            float4 b0 = *(const float4*)&Bs[kk][tx * GTN];
            float ra[8] = {a0.x, a0.y, a0.z, a0.w, a1.x, a1.y, a1.z, a1.w};
            float rb[4] = {b0.x, b0.y, b0.z, b0.w};
#pragma unroll
            for (int i = 0; i < GTM; i++)
#pragma unroll
                for (int j = 0; j < GTN; j++) acc[i][j] += ra[i] * rb[j];
        }
        __syncthreads();
    }
#pragma unroll
    for (int i = 0; i < GTM; i++) {
        float4 o = make_float4(acc[i][0], acc[i][1], acc[i][2], acc[i][3]);
        *(float4*)(C + (size_t)(m0 + ty * GTM + i) * ldc + n0 + tx * GTN) = o;
    }
}

// -------- NN GEMM: C[m,n] = sum_k A[m,k] * B[k,n] --------
__global__ __launch_bounds__(256) void gemm_nn(
    const float* __restrict__ A, const float* __restrict__ Bv, float* __restrict__ C,
    int M, int Nn, int K, int lda, int ldb, int ldc,
    int nzi, long long sAo, long long sAi, long long sBo, long long sBi,
    long long sCo, long long sCi)
{
    int z = blockIdx.z;
    A  += (long long)(z / nzi) * sAo + (long long)(z % nzi) * sAi;
    Bv += (long long)(z / nzi) * sBo + (long long)(z % nzi) * sBi;
    C  += (long long)(z / nzi) * sCo + (long long)(z % nzi) * sCi;

    __shared__ float As[GBK][GBM];
    __shared__ float Bs[GBK][GBN];

    int t  = threadIdx.x;
    int m0 = blockIdx.y * GBM;
    int n0 = blockIdx.x * GBN;
    int ty = t >> 4;
    int tx = t & 15;

    float acc[GTM][GTN];
#pragma unroll
    for (int i = 0; i < GTM; i++)
#pragma unroll
        for (int j = 0; j < GTN; j++) acc[i][j] = 0.f;

    int ar = t >> 2;        // 0..63 (A rows)
    int ac = (t & 3) * 4;
    int br = t >> 4;        // 0..15 (B k-rows)
    int bc = (t & 15) * 4;  // 0..60

    for (int kt = 0; kt < K; kt += GBK) {
#pragma unroll
        for (int r = 0; r < 2; r++) {
            int row = ar + r * 64;
            float4 av = *(const float4*)(A + (size_t)(m0 + row) * lda + kt + ac);
            As[ac + 0][row] = av.x; As[ac + 1][row] = av.y;
            As[ac + 2][row] = av.z; As[ac + 3][row] = av.w;
        }
        {
            float4 bv = *(const float4*)(Bv + (size_t)(kt + br) * ldb + n0 + bc);
            *(float4*)&Bs[br][bc] = bv;
        }
        __syncthreads();
#pragma unroll
        for (int kk = 0; kk < GBK; kk++) {
            float4 a0 = *(const float4*)&As[kk][ty * GTM];
            float4 a1 = *(const float4*)&As[kk][ty * GTM + 4];
            float4 b0 = *(const float4*)&Bs[kk][tx * GTN];
            float ra[8] = {a0.x, a0.y, a0.z, a0.w, a1.x, a1.y, a1.z, a1.w};
            float rb[4] = {b0.x, b0.y, b0.z, b0.w};
#pragma unroll
            for (int i = 0; i < GTM; i++)
#pragma unroll
                for (int j = 0; j < GTN; j++) acc[i][j] += ra[i] * rb[j];
        }
        __syncthreads();
    }
#pragma unroll
    for (int i = 0; i < GTM; i++) {
        float4 o = make_float4(acc[i][0], acc[i][1], acc[i][2], acc[i][3]);
        *(float4*)(C + (size_t)(m0 + ty * GTM + i) * ldc + n0 + tx * GTN) = o;
    }
}

// -------- per-token RMSNorm + 2D RoPE (q,k) / RMSNorm (v) --------
// One block per token; warp w owns head w (12 warps = 384 threads).
// Lane l holds dims l and l+32 of the 64-dim head.
__global__ __launch_bounds__(384) void norm_rope_kernel(
    const int* __restrict__ pos, const float* __restrict__ qs, const float* __restrict__ ks)
{
    int token = blockIdx.x;
    int warp  = threadIdx.x >> 5;
    int lane  = threadIdx.x & 31;
    if (warp >= HH) return;

    size_t base = (size_t)token * HD + (size_t)warp * DHH;
    float p0 = (float)pos[token * 2 + 0];
    float p1 = (float)pos[token * 2 + 1];

    // inv freq: 100^(-(i mod 16)/16), i = lane (same for both 32-halves)
    float inv = powf(100.f, -(float)(lane & 15) / 16.f);
    float s0, c0, s1, c1;
    sincosf(p0 * inv, &s0, &c0);
    sincosf(p1 * inv, &s1, &c1);
    float sgn = (lane < 16) ? -1.f : 1.f;

    // ---- Q: rmsnorm(scale) + rope ----
    {
        float x0 = g_q[base + lane], x1 = g_q[base + 32 + lane];
        float ss = x0 * x0 + x1 * x1;
#pragma unroll
        for (int o = 16; o; o >>= 1) ss += __shfl_xor_sync(0xffffffffu, ss, o);
        float r = rsqrtf(ss * (1.f / 64.f) + 1e-6f);
        float n0 = x0 * r * qs[lane];
        float n1 = x1 * r * qs[lane + 32];
        float pr0 = __shfl_xor_sync(0xffffffffu, n0, 16);
        float pr1 = __shfl_xor_sync(0xffffffffu, n1, 16);
        g_q[base + lane]      = n0 * c0 + sgn * pr0 * s0;
        g_q[base + 32 + lane] = n1 * c1 + sgn * pr1 * s1;
    }
    // ---- K: rmsnorm(scale) + rope ----
    {
        float x0 = g_k[base + lane], x1 = g_k[base + 32 + lane];
        float ss = x0 * x0 + x1 * x1;
#pragma unroll
        for (int o = 16; o; o >>= 1) ss += __shfl_xor_sync(0xffffffffu, ss, o);
        float r = rsqrtf(ss * (1.f / 64.f) + 1e-6f);
        float n0 = x0 * r * ks[lane];
        float n1 = x1 * r * ks[lane + 32];
        float pr0 = __shfl_xor_sync(0xffffffffu, n0, 16);
        float pr1 = __shfl_xor_sync(0xffffffffu, n1, 16);
        g_k[base + lane]      = n0 * c0 + sgn * pr0 * s0;
        g_k[base + 32 + lane] = n1 * c1 + sgn * pr1 * s1;
    }
    // ---- V: rmsnorm only ----
    {
        float x0 = g_v[base + lane], x1 = g_v[base + 32 + lane];
        float ss = x0 * x0 + x1 * x1;
#pragma unroll
        for (int o = 16; o; o >>= 1) ss += __shfl_xor_sync(0xffffffffu, ss, o);
        float r = rsqrtf(ss * (1.f / 64.f) + 1e-6f);
        g_v[base + lane]      = x0 * r;
        g_v[base + 32 + lane] = x1 * r;
    }
}

// -------- row softmax over 1024 (in-place on g_s) --------
__global__ __launch_bounds__(256) void softmax_kernel(float* __restrict__ S)
{
    size_t row = blockIdx.x;
    float* p = S + row * SEQ;
    int t = threadIdx.x;

    float v[4];
    float mx = -1e30f;
#pragma unroll
    for (int i = 0; i < 4; i++) { v[i] = p[t + i * 256]; mx = fmaxf(mx, v[i]); }

    __shared__ float redm[8];
    __shared__ float reds[8];
#pragma unroll
    for (int o = 16; o; o >>= 1) mx = fmaxf(mx, __shfl_xor_sync(0xffffffffu, mx, o));
    if ((t & 31) == 0) redm[t >> 5] = mx;
    __syncthreads();
    if (t < 8) {
        float m = redm[t];
#pragma unroll
        for (int o = 4; o; o >>= 1) m = fmaxf(m, __shfl_xor_sync(0xffu, m, o));
        redm[t] = m;
    }
    __syncthreads();
    mx = redm[0];

    float sum = 0.f;
#pragma unroll
    for (int i = 0; i < 4; i++) { v[i] = __expf(v[i] - mx); sum += v[i]; }
#pragma unroll
    for (int o = 16; o; o >>= 1) sum += __shfl_xor_sync(0xffffffffu, sum, o);
    if ((t & 31) == 0) reds[t >> 5] = sum;
    __syncthreads();
    if (t < 8) {
        float s = reds[t];
#pragma unroll
        for (int o = 4; o; o >>= 1) s += __shfl_xor_sync(0xffu, s, o);
        reds[t] = s;
    }
    __syncthreads();
    float invs = 1.f / reds[0];
#pragma unroll
    for (int i = 0; i < 4; i++) p[t + i * 256] = v[i] * invs;
}

// -------- host launch --------
extern "C" void kernel_launch(void* const* d_in, const int* in_sizes, int n_in,
                              void* d_out, int out_size)
{
    const float* X   = (const float*)d_in[0];
    const int*   pos = (const int*)  d_in[1];
    const float* Wq  = (const float*)d_in[2];
    const float* Wk  = (const float*)d_in[3];
    const float* Wv  = (const float*)d_in[4];
    const float* Wo  = (const float*)d_in[5];
    const float* qs  = (const float*)d_in[6];
    const float* ks  = (const float*)d_in[7];
    float* out = (float*)d_out;

    float *gq, *gk, *gv, *go, *gs;
    cudaGetSymbolAddress((void**)&gq, g_q);
    cudaGetSymbolAddress((void**)&gk, g_k);
    cudaGetSymbolAddress((void**)&gv, g_v);
    cudaGetSymbolAddress((void**)&go, g_o);
    cudaGetSymbolAddress((void**)&gs, g_s);

    dim3 blk(256);

    // 1) QKV projections: [8192,768] = X[8192,768] @ W[768,768]^T
    dim3 gproj(DD / GBN, TOK / GBM, 1);
    gemm_nt<<<gproj, blk>>>(X, Wq, gq, TOK, DD, DD, DD, DD, DD, 1, 0, 0, 0, 0, 0, 0);
    gemm_nt<<<gproj, blk>>>(X, Wk, gk, TOK, DD, DD, DD, DD, DD, 1, 0, 0, 0, 0, 0, 0);
    gemm_nt<<<gproj, blk>>>(X, Wv, gv, TOK, DD, DD, DD, DD, DD, 1, 0, 0, 0, 0, 0, 0);

    // 2) RMSNorm + RoPE
    norm_rope_kernel<<<TOK, 384>>>(pos, qs, ks);

    // 3) scores[b,h] = Q[b,:,h,:] @ K[b,:,h,:]^T   (96 batched 1024x1024x64)
    dim3 gsc(SEQ / GBN, SEQ / GBM, BB * HH);
    gemm_nt<<<gsc, blk>>>(gq, gk, gs, SEQ, SEQ, DHH, HD, HD, SEQ,
                          HH,
                          (long long)SEQ * HD, (long long)DHH,
                          (long long)SEQ * HD, (long long)DHH,
                          (long long)HH * SEQ * SEQ, (long long)SEQ * SEQ);

    // 4) softmax rows
    softmax_kernel<<<BB * HH * SEQ, 256>>>(gs);

    // 5) O[b,:,h,:] = P[b,h] @ V[b,:,h,:]   (96 batched 1024x64x1024)
    dim3 gpv(DHH / GBN, SEQ / GBM, BB * HH);
    gemm_nn<<<gpv, blk>>>(gs, gv, go, SEQ, DHH, SEQ, SEQ, HD, HD,
                          HH,
                          (long long)HH * SEQ * SEQ, (long long)SEQ * SEQ,
                          (long long)SEQ * HD, (long long)DHH,
                          (long long)SEQ * HD, (long long)DHH);

    // 6) out = O @ Wo^T
    gemm_nt<<<gproj, blk>>>(go, Wo, out, TOK, DD, DD, DD, DD, DD, 1, 0, 0, 0, 0, 0, 0);
}

// round 3
// speedup vs baseline: 1.0001x; 1.0001x over previous
#include <cuda_runtime.h>
#include <math.h>

#define BB   8
#define SEQ  1024
#define DD   768
#define HH   12
#define DHH  64
#define HD   768            // HH*DHH
#define TOK  (BB*SEQ)       // 8192

// -------- scratch (static device globals; no allocs allowed) --------
__device__ float g_q[(size_t)TOK*HD];
__device__ float g_k[(size_t)TOK*HD];
__device__ float g_v[(size_t)TOK*HD];
__device__ float g_o[(size_t)TOK*HD];
__device__ float g_s[(size_t)BB*HH*SEQ*SEQ];   // 402 MB attention scores

// -------- tiled fp32 GEMM: C[m,n] = sum_k A[m,k] * B[n,k]  (NT) --------
// BM=128, BN=64, BK=16, 256 threads, 8x4 per-thread microtile.
// Batched via blockIdx.z with two-level (outer/inner) stride decomposition:
//   off = (z / nzi) * s?o + (z % nzi) * s?i
#define GBM 128
#define GBN 64
#define GBK 16
#define GTM 8
#define GTN 4

__global__ __launch_bounds__(256) void gemm_nt(
    const float* __restrict__ A, const float* __restrict__ Bw, float* __restrict__ C,
    int M, int Nn, int K, int lda, int ldb, int ldc,
    int nzi, long long sAo, long long sAi, long long sBo, long long sBi,
    long long sCo, long long sCi)
{
    int z = blockIdx.z;
    A  += (long long)(z / nzi) * sAo + (long long)(z % nzi) * sAi;
    Bw += (long long)(z / nzi) * sBo + (long long)(z % nzi) * sBi;
    C  += (long long)(z / nzi) * sCo + (long long)(z % nzi) * sCi;

    __shared__ float As[GBK][GBM];
    __shared__ float Bs[GBK][GBN];

    int t  = threadIdx.x;
    int m0 = blockIdx.y * GBM;
    int n0 = blockIdx.x * GBN;
    int ty = t >> 4;        // 0..15
    int tx = t & 15;        // 0..15

    float acc[GTM][GTN];
#pragma unroll
    for (int i = 0; i < GTM; i++)
#pragma unroll
        for (int j = 0; j < GTN; j++) acc[i][j] = 0.f;

    int ar = t >> 2;        // 0..63
    int ac = (t & 3) * 4;   // 0,4,8,12

    for (int kt = 0; kt < K; kt += GBK) {
#pragma unroll
        for (int r = 0; r < 2; r++) {
            int row = ar + r * 64;
            float4 av = *(const float4*)(A + (size_t)(m0 + row) * lda + kt + ac);
            As[ac + 0][row] = av.x; As[ac + 1][row] = av.y;
            As[ac + 2][row] = av.z; As[ac + 3][row] = av.w;
        }
        {
            float4 bv = *(const float4*)(Bw + (size_t)(n0 + ar) * ldb + kt + ac);
            Bs[ac + 0][ar] = bv.x; Bs[ac + 1][ar] = bv.y;
            Bs[ac + 2][ar] = bv.z; Bs[ac + 3][ar] = bv.w;
        }
        __syncthreads();
#pragma unroll
        for (int kk = 0; kk < GBK; kk++) {
            float4 a0 = *(const float4*)&As[kk][ty * GTM];
            float4 a1 = *(const float4*)&As[kk][ty * GTM + 4];
            float4 b0 = *(const float4*)&Bs[kk][tx * GTN];
            float ra[8] = {a0.x, a0.y, a0.z, a0.w, a1.x, a1.y, a1.z, a1.w};
            float rb[4] = {b0.x, b0.y, b0.z, b0.w};
#pragma unroll
            for (int i = 0; i < GTM; i++)
#pragma unroll
                for (int j = 0; j < GTN; j++) acc[i][j] += ra[i] * rb[j];
        }
        __syncthreads();
    }
#pragma unroll
    for (int i = 0; i < GTM; i++) {
        float4 o = make_float4(acc[i][0], acc[i][1], acc[i][2], acc[i][3]);
        *(float4*)(C + (size_t)(m0 + ty * GTM + i) * ldc + n0 + tx * GTN) = o;
    }
}

// -------- NN GEMM: C[m,n] = sum_k A[m,k] * B[k,n] --------
__global__ __launch_bounds__(256) void gemm_nn(
    const float* __restrict__ A, const float* __restrict__ Bv, float* __restrict__ C,
    int M, int Nn, int K, int lda, int ldb, int ldc,
    int nzi, long long sAo, long long sAi, long long sBo, long long sBi,
    long long sCo, long long sCi)
{
    int z = blockIdx.z;
    A  += (long long)(z / nzi) * sAo + (long long)(z % nzi) * sAi;
    Bv += (long long)(z / nzi) * sBo + (long long)(z % nzi) * sBi;
    C  += (long long)(z / nzi) * sCo + (long long)(z % nzi) * sCi;

    __shared__ float As[GBK][GBM];
    __shared__ float Bs[GBK][GBN];

    int t  = threadIdx.x;
    int m0 = blockIdx.y * GBM;
    int n0 = blockIdx.x * GBN;
    int ty = t >> 4;
    int tx = t & 15;

    float acc[GTM][GTN];
#pragma unroll
    for (int i = 0; i < GTM; i++)
#pragma unroll
        for (int j = 0; j < GTN; j++) acc[i][j] = 0.f;

    int ar = t >> 2;        // 0..63 (A rows)
    int ac = (t & 3) * 4;
    int br = t >> 4;        // 0..15 (B k-rows)
    int bc = (t & 15) * 4;  // 0..60

    for (int kt = 0; kt < K; kt += GBK) {
#pragma unroll
        for (int r = 0; r < 2; r++) {
            int row = ar + r * 64;
            float4 av = *(const float4*)(A + (size_t)(m0 + row) * lda + kt + ac);
            As[ac + 0][row] = av.x; As[ac + 1][row] = av.y;
            As[ac + 2][row] = av.z; As[ac + 3][row] = av.w;
        }
        {
            float4 bv = *(const float4*)(Bv + (size_t)(kt + br) * ldb + n0 + bc);
            *(float4*)&Bs[br][bc] = bv;
        }
        __syncthreads();
#pragma unroll
        for (int kk = 0; kk < GBK; kk++) {
            float4 a0 = *(const float4*)&As[kk][ty * GTM];
            float4 a1 = *(const float4*)&As[kk][ty * GTM + 4];
            float4 b0 = *(const float4*)&Bs[kk][tx * GTN];
            float ra[8] = {a0.x, a0.y, a0.z, a0.w, a1.x, a1.y, a1.z, a1.w};
            float rb[4] = {b0.x, b0.y, b0.z, b0.w};
#pragma unroll
            for (int i = 0; i < GTM; i++)
#pragma unroll
                for (int j = 0; j < GTN; j++) acc[i][j] += ra[i] * rb[j];
        }
        __syncthreads();
    }
#pragma unroll
    for (int i = 0; i < GTM; i++) {
        float4 o = make_float4(acc[i][0], acc[i][1], acc[i][2], acc[i][3]);
        *(float4*)(C + (size_t)(m0 + ty * GTM + i) * ldc + n0 + tx * GTN) = o;
    }
}

// -------- per-token RMSNorm + 2D RoPE (q,k) / RMSNorm (v) --------
// One block per token; warp w owns head w (12 warps = 384 threads).
// Lane l holds dims l and l+32 of the 64-dim head.
__global__ __launch_bounds__(384) void norm_rope_kernel(
    const int* __restrict__ pos, const float* __restrict__ qs, const float* __restrict__ ks)
{
    int token = blockIdx.x;
    int warp  = threadIdx.x >> 5;
    int lane  = threadIdx.x & 31;
    if (warp >= HH) return;

    size_t base = (size_t)token * HD + (size_t)warp * DHH;
    float p0 = (float)pos[token * 2 + 0];
    float p1 = (float)pos[token * 2 + 1];

    // inv freq: 100^(-(i mod 16)/16), i = lane (same for both 32-halves)
    float inv = powf(100.f, -(float)(lane & 15) / 16.f);
    float s0, c0, s1, c1;
    sincosf(p0 * inv, &s0, &c0);
    sincosf(p1 * inv, &s1, &c1);
    float sgn = (lane < 16) ? -1.f : 1.f;

    // ---- Q: rmsnorm(scale) + rope ----
    {
        float x0 = g_q[base + lane], x1 = g_q[base + 32 + lane];
        float ss = x0 * x0 + x1 * x1;
#pragma unroll
        for (int o = 16; o; o >>= 1) ss += __shfl_xor_sync(0xffffffffu, ss, o);
        float r = rsqrtf(ss * (1.f / 64.f) + 1e-6f);
        float n0 = x0 * r * qs[lane];
        float n1 = x1 * r * qs[lane + 32];
        float pr0 = __shfl_xor_sync(0xffffffffu, n0, 16);
        float pr1 = __shfl_xor_sync(0xffffffffu, n1, 16);
        g_q[base + lane]      = n0 * c0 + sgn * pr0 * s0;
        g_q[base + 32 + lane] = n1 * c1 + sgn * pr1 * s1;
    }
    // ---- K: rmsnorm(scale) + rope ----
    {
        float x0 = g_k[base + lane], x1 = g_k[base + 32 + lane];
        float ss = x0 * x0 + x1 * x1;
#pragma unroll
        for (int o = 16; o; o >>= 1) ss += __shfl_xor_sync(0xffffffffu, ss, o);
        float r = rsqrtf(ss * (1.f / 64.f) + 1e-6f);
        float n0 = x0 * r * ks[lane];
        float n1 = x1 * r * ks[lane + 32];
        float pr0 = __shfl_xor_sync(0xffffffffu, n0, 16);
        float pr1 = __shfl_xor_sync(0xffffffffu, n1, 16);
        g_k[base + lane]      = n0 * c0 + sgn * pr0 * s0;
        g_k[base + 32 + lane] = n1 * c1 + sgn * pr1 * s1;
    }
    // ---- V: rmsnorm only ----
    {
        float x0 = g_v[base + lane], x1 = g_v[base + 32 + lane];
        float ss = x0 * x0 + x1 * x1;
#pragma unroll
        for (int o = 16; o; o >>= 1) ss += __shfl_xor_sync(0xffffffffu, ss, o);
        float r = rsqrtf(ss * (1.f / 64.f) + 1e-6f);
        g_v[base + lane]      = x0 * r;
        g_v[base + 32 + lane] = x1 * r;
    }
}

// -------- row softmax over 1024 (in-place on g_s) --------
__global__ __launch_bounds__(256) void softmax_kernel(float* __restrict__ S)
{
    size_t row = blockIdx.x;
    float* p = S + row * SEQ;
    int t = threadIdx.x;

    float v[4];
    float mx = -1e30f;
#pragma unroll
    for (int i = 0; i < 4; i++) { v[i] = p[t + i * 256]; mx = fmaxf(mx, v[i]); }

    __shared__ float redm[8];
    __shared__ float reds[8];
#pragma unroll
    for (int o = 16; o; o >>= 1) mx = fmaxf(mx, __shfl_xor_sync(0xffffffffu, mx, o));
    if ((t & 31) == 0) redm[t >> 5] = mx;
    __syncthreads();
    if (t < 8) {
        float m = redm[t];
#pragma unroll
        for (int o = 4; o; o >>= 1) m = fmaxf(m, __shfl_xor_sync(0xffu, m, o));
        redm[t] = m;
    }
    __syncthreads();
    mx = redm[0];

    float sum = 0.f;
#pragma unroll
    for (int i = 0; i < 4; i++) { v[i] = __expf(v[i] - mx); sum += v[i]; }
#pragma unroll
    for (int o = 16; o; o >>= 1) sum += __shfl_xor_sync(0xffffffffu, sum, o);
    if ((t & 31) == 0) reds[t >> 5] = sum;
    __syncthreads();
    if (t < 8) {
        float s = reds[t];
#pragma unroll
        for (int o = 4; o; o >>= 1) s += __shfl_xor_sync(0xffu, s, o);
        reds[t] = s;
    }
    __syncthreads();
    float invs = 1.f / reds[0];
#pragma unroll
    for (int i = 0; i < 4; i++) p[t + i * 256] = v[i] * invs;
}

// -------- host launch --------
extern "C" void kernel_launch(void* const* d_in, const int* in_sizes, int n_in,
                              void* d_out, int out_size)
{
    const float* X   = (const float*)d_in[0];
    const int*   pos = (const int*)  d_in[1];
    const float* Wq  = (const float*)d_in[2];
    const float* Wk  = (const float*)d_in[3];
    const float* Wv  = (const float*)d_in[4];
    const float* Wo  = (const float*)d_in[5];
    const float* qs  = (const float*)d_in[6];
    const float* ks  = (const float*)d_in[7];
    float* out = (float*)d_out;

    float *gq, *gk, *gv, *go, *gs;
    cudaGetSymbolAddress((void**)&gq, g_q);
    cudaGetSymbolAddress((void**)&gk, g_k);
    cudaGetSymbolAddress((void**)&gv, g_v);
    cudaGetSymbolAddress((void**)&go, g_o);
    cudaGetSymbolAddress((void**)&gs, g_s);

    dim3 blk(256);

    // 1) QKV projections: [8192,768] = X[8192,768] @ W[768,768]^T
    dim3 gproj(DD / GBN, TOK / GBM, 1);
    gemm_nt<<<gproj, blk>>>(X, Wq, gq, TOK, DD, DD, DD, DD, DD, 1, 0, 0, 0, 0, 0, 0);
    gemm_nt<<<gproj, blk>>>(X, Wk, gk, TOK, DD, DD, DD, DD, DD, 1, 0, 0, 0, 0, 0, 0);
    gemm_nt<<<gproj, blk>>>(X, Wv, gv, TOK, DD, DD, DD, DD, DD, 1, 0, 0, 0, 0, 0, 0);

    // 2) RMSNorm + RoPE
    norm_rope_kernel<<<TOK, 384>>>(pos, qs, ks);

    // 3) scores[b,h] = Q[b,:,h,:] @ K[b,:,h,:]^T   (96 batched 1024x1024x64)
    dim3 gsc(SEQ / GBN, SEQ / GBM, BB * HH);
    gemm_nt<<<gsc, blk>>>(gq, gk, gs, SEQ, SEQ, DHH, HD, HD, SEQ,
                          HH,
                          (long long)SEQ * HD, (long long)DHH,
                          (long long)SEQ * HD, (long long)DHH,
                          (long long)HH * SEQ * SEQ, (long long)SEQ * SEQ);

    // 4) softmax rows
    softmax_kernel<<<BB * HH * SEQ, 256>>>(gs);

    // 5) O[b,:,h,:] = P[b,h] @ V[b,:,h,:]   (96 batched 1024x64x1024)
    dim3 gpv(DHH / GBN, SEQ / GBM, BB * HH);
    gemm_nn<<<gpv, blk>>>(gs, gv, go, SEQ, DHH, SEQ, SEQ, HD, HD,
                          HH,
                          (long long)HH * SEQ * SEQ, (long long)SEQ * SEQ,
                          (long long)SEQ * HD, (long long)DHH,
                          (long long)SEQ * HD, (long long)DHH);

    // 6) out = O @ Wo^T
    gemm_nt<<<gproj, blk>>>(go, Wo, out, TOK, DD, DD, DD, DD, DD, 1, 0, 0, 0, 0, 0, 0);
}